// round 13
// baseline (speedup 1.0000x reference)
#include <cuda_runtime.h>
#include <cuda_bf16.h>

#define HIDDEN 2048
#define INTER  1408
#define TOP_K  4

// Scratch for weighted intermediate activations: topk_w[e] * silu(gate)*up
__device__ float g_inter[TOP_K * INTER];

// ---------------------------------------------------------------------------
// Kernel 1 (identical to the 25.06us best): gate/up GEMV + SiLU with
// embedded FULL L2 prefetch of the down matrices, issued up front.
// Block (bx, e) prefetches bytes [bx*64K, (bx+1)*64K) of down[topk_idx[e]]
// (176 x 64 KB = 11.53 MB per expert, exact): the 46 MB down fetch streams
// concurrently with the 92 MB gate/up stream in one DRAM window.
// grid: (176, 4), block: 256 threads (8 warps, 1 row per warp)
// ---------------------------------------------------------------------------
__global__ __launch_bounds__(256)
void moe_gate_up_kernel(const float* __restrict__ x,
                        const int*   __restrict__ topk_idx,
                        const float* __restrict__ topk_w,
                        const float* __restrict__ gate_all,
                        const float* __restrict__ up_all,
                        const float* __restrict__ down_all)
{
    __shared__ float4 x_s[HIDDEN / 4];   // 8 KB

    const int tid  = threadIdx.x;
    const int lane = tid & 31;
    const int warp = tid >> 5;
    const int e    = blockIdx.y;                // expert slot 0..3
    const long long ex = topk_idx[e];

    // --- Embedded full prefetch of this expert's down block slice
    {
        const char* dbase = reinterpret_cast<const char*>(
            down_all + ex * (long long)(HIDDEN * INTER));
        const long long off = (long long)blockIdx.x * 65536 + tid * 128;
        asm volatile("prefetch.global.L2 [%0];" :: "l"(dbase + off));
        asm volatile("prefetch.global.L2 [%0];" :: "l"(dbase + off + 32768));
    }

    // Stage x into shared memory: 512 float4 / 256 threads = 2 each
    const float4* x4 = reinterpret_cast<const float4*>(x);
    x_s[tid]       = x4[tid];
    x_s[tid + 256] = x4[tid + 256];
    __syncthreads();

    const int row = blockIdx.x * 8 + warp;      // 0..1407

    const float4* g4 = reinterpret_cast<const float4*>(
        gate_all + (ex * INTER + row) * (long long)HIDDEN);
    const float4* u4 = reinterpret_cast<const float4*>(
        up_all   + (ex * INTER + row) * (long long)HIDDEN);

    float gacc = 0.f, uacc = 0.f;
    // 512 float4 per row, 32 lanes -> 16 iterations
#pragma unroll
    for (int j = 0; j < 16; j++) {
        const int idx = j * 32 + lane;
        const float4 xv = x_s[idx];
        const float4 gv = __ldcs(g4 + idx);   // streaming: evict-first
        const float4 uv = __ldcs(u4 + idx);
        gacc += gv.x * xv.x + gv.y * xv.y + gv.z * xv.z + gv.w * xv.w;
        uacc += uv.x * xv.x + uv.y * xv.y + uv.z * xv.z + uv.w * xv.w;
    }

    // warp reduce
#pragma unroll
    for (int off = 16; off > 0; off >>= 1) {
        gacc += __shfl_xor_sync(0xFFFFFFFFu, gacc, off);
        uacc += __shfl_xor_sync(0xFFFFFFFFu, uacc, off);
    }

    if (lane == 0) {
        const float w = topk_w[e];
        const float silu = gacc / (1.0f + __expf(-gacc));
        g_inter[e * INTER + row] = w * silu * uacc;
    }
}

// ---------------------------------------------------------------------------
// Kernel 2: out[h] = sum_e dot(down[ex_e][h][:], g_inter[e][:])
// 512-thread blocks serving 8 h each (2 warps per h, expert pairs {0,1} and
// {2,3}): same 4096 warp-tasks as before, but HALF the blocks -> gi staging
// L2 traffic drops 11.5 MB -> 5.8 MB. Fixed-order smem combine:
// deterministic, no atomics, no memset. Down reads hit L2 (prefetched).
// grid: 256, block: 512 threads (16 warps: warp = 2*h_local + pair)
// ---------------------------------------------------------------------------
__global__ __launch_bounds__(512)
void moe_down_kernel(const int*   __restrict__ topk_idx,
                     const float* __restrict__ down_all,
                     float*       __restrict__ out)
{
    __shared__ float4 gi_s[TOP_K * INTER / 4];   // 1408 float4 = 22.5 KB
    __shared__ float  partial[16];

    const int tid  = threadIdx.x;
    const int lane = tid & 31;
    const int warp = tid >> 5;               // 0..15
    const int hloc = warp >> 1;              // 0..7
    const int p    = warp & 1;               // expert pair 0..1

    // Stage g_inter: 1408 float4 / 512 threads
    const float4* gi4 = reinterpret_cast<const float4*>(g_inter);
    for (int k = tid; k < TOP_K * INTER / 4; k += 512)
        gi_s[k] = gi4[k];
    __syncthreads();

    const int h = blockIdx.x * 8 + hloc;     // 0..2047

    const long long e0 = topk_idx[2 * p];
    const long long e1 = topk_idx[2 * p + 1];
    const float4* d0 = reinterpret_cast<const float4*>(
        down_all + (e0 * HIDDEN + h) * (long long)INTER);
    const float4* d1 = reinterpret_cast<const float4*>(
        down_all + (e1 * HIDDEN + h) * (long long)INTER);
    const float4* v0p = gi_s + 2 * p * 352;
    const float4* v1p = gi_s + (2 * p + 1) * 352;

    float acc0 = 0.f, acc1 = 0.f;
    // 352 float4 per expert row, 32 lanes -> 11 iterations x 2 experts
#pragma unroll
    for (int j = 0; j < 11; j++) {
        const int idx = j * 32 + lane;
        const float4 a0 = __ldg(d0 + idx);
        const float4 a1 = __ldg(d1 + idx);
        const float4 v0 = v0p[idx];
        const float4 v1 = v1p[idx];
        acc0 += a0.x * v0.x + a0.y * v0.y + a0.z * v0.z + a0.w * v0.w;
        acc1 += a1.x * v1.x + a1.y * v1.y + a1.z * v1.z + a1.w * v1.w;
    }

    float acc = acc0 + acc1;
#pragma unroll
    for (int off = 16; off > 0; off >>= 1)
        acc += __shfl_xor_sync(0xFFFFFFFFu, acc, off);

    if (lane == 0) partial[warp] = acc;
    __syncthreads();

    if (tid < 8)
        out[blockIdx.x * 8 + tid] = partial[2 * tid] + partial[2 * tid + 1];
}

extern "C" void kernel_launch(void* const* d_in, const int* in_sizes, int n_in,
                              void* d_out, int out_size)
{
    const float* x        = (const float*)d_in[0];   // (1, 2048, 1, 1)
    const int*   topk_idx = (const int*)  d_in[1];   // (4,)
    const float* topk_w   = (const float*)d_in[2];   // (4,)
    const float* gate_all = (const float*)d_in[3];   // (60, 1408, 2048)
    const float* up_all   = (const float*)d_in[4];   // (60, 1408, 2048)
    const float* down_all = (const float*)d_in[5];   // (60, 2048, 1408)
    float* out = (float*)d_out;                      // (1, 2048, 1, 1)

    dim3 grid1(INTER / 8, TOP_K);
    moe_gate_up_kernel<<<grid1, 256>>>(x, topk_idx, topk_w,
                                       gate_all, up_all, down_all);

    moe_down_kernel<<<HIDDEN / 8, 512>>>(topk_idx, down_all, out);
}

// round 14
// speedup vs baseline: 1.0115x; 1.0115x over previous
#include <cuda_runtime.h>
#include <cuda_bf16.h>

#define HIDDEN 2048
#define INTER  1408
#define TOP_K  4

// Scratch for weighted intermediate activations: topk_w[e] * silu(gate)*up
__device__ float g_inter[TOP_K * INTER];

// ---------------------------------------------------------------------------
// Kernel 1: gate/up GEMV + SiLU with embedded FULL L2 prefetch of the down
// matrices, issued up front with ::evict_last so the prefetched lines are
// retained at highest L2 priority while the 92 MB gate/up stream (evict-
// first __ldcs) flows past them. Block (bx, e) prefetches bytes
// [bx*64K, (bx+1)*64K) of down[topk_idx[e]] (176 x 64 KB = 11.53 MB per
// expert, exact).
// grid: (176, 4), block: 256 threads (8 warps, 1 row per warp)
// ---------------------------------------------------------------------------
__global__ __launch_bounds__(256)
void moe_gate_up_kernel(const float* __restrict__ x,
                        const int*   __restrict__ topk_idx,
                        const float* __restrict__ topk_w,
                        const float* __restrict__ gate_all,
                        const float* __restrict__ up_all,
                        const float* __restrict__ down_all)
{
    __shared__ float4 x_s[HIDDEN / 4];   // 8 KB

    const int tid  = threadIdx.x;
    const int lane = tid & 31;
    const int warp = tid >> 5;
    const int e    = blockIdx.y;                // expert slot 0..3
    const long long ex = topk_idx[e];

    // --- Embedded full prefetch (evict_last: pin in L2 until kernel 2)
    {
        const char* dbase = reinterpret_cast<const char*>(
            down_all + ex * (long long)(HIDDEN * INTER));
        const long long off = (long long)blockIdx.x * 65536 + tid * 128;
        asm volatile("prefetch.global.L2::evict_last [%0];" :: "l"(dbase + off));
        asm volatile("prefetch.global.L2::evict_last [%0];" :: "l"(dbase + off + 32768));
    }

    // Stage x into shared memory: 512 float4 / 256 threads = 2 each
    const float4* x4 = reinterpret_cast<const float4*>(x);
    x_s[tid]       = x4[tid];
    x_s[tid + 256] = x4[tid + 256];
    __syncthreads();

    const int row = blockIdx.x * 8 + warp;      // 0..1407

    const float4* g4 = reinterpret_cast<const float4*>(
        gate_all + (ex * INTER + row) * (long long)HIDDEN);
    const float4* u4 = reinterpret_cast<const float4*>(
        up_all   + (ex * INTER + row) * (long long)HIDDEN);

    float gacc = 0.f, uacc = 0.f;
    // 512 float4 per row, 32 lanes -> 16 iterations
#pragma unroll
    for (int j = 0; j < 16; j++) {
        const int idx = j * 32 + lane;
        const float4 xv = x_s[idx];
        const float4 gv = __ldcs(g4 + idx);   // streaming: evict-first
        const float4 uv = __ldcs(u4 + idx);
        gacc += gv.x * xv.x + gv.y * xv.y + gv.z * xv.z + gv.w * xv.w;
        uacc += uv.x * xv.x + uv.y * xv.y + uv.z * xv.z + uv.w * xv.w;
    }

    // warp reduce
#pragma unroll
    for (int off = 16; off > 0; off >>= 1) {
        gacc += __shfl_xor_sync(0xFFFFFFFFu, gacc, off);
        uacc += __shfl_xor_sync(0xFFFFFFFFu, uacc, off);
    }

    if (lane == 0) {
        const float w = topk_w[e];
        const float silu = gacc / (1.0f + __expf(-gacc));
        g_inter[e * INTER + row] = w * silu * uacc;
    }
}

// ---------------------------------------------------------------------------
// Kernel 2 (the twice-measured 25.06us shape): out[h] =
// sum_e dot(down[ex_e][h][:], g_inter[e][:]).
// Two warps per h (expert pairs {0,1} and {2,3}), 4 h per block, gi staged
// in smem, fixed-order smem combine: deterministic, no atomics, no memset.
// Down reads hit L2 (prefetched + pinned by kernel 1).
// grid: 512, block: 256 threads (8 warps: warp = 2*h_local + pair)
// ---------------------------------------------------------------------------
__global__ __launch_bounds__(256)
void moe_down_kernel(const int*   __restrict__ topk_idx,
                     const float* __restrict__ down_all,
                     float*       __restrict__ out)
{
    __shared__ float4 gi_s[TOP_K * INTER / 4];   // 1408 float4 = 22.5 KB
    __shared__ float  partial[8];

    const int tid  = threadIdx.x;
    const int lane = tid & 31;
    const int warp = tid >> 5;
    const int hloc = warp >> 1;              // 0..3
    const int p    = warp & 1;               // expert pair 0..1

    // Stage g_inter: 1408 float4 / 256 threads
    const float4* gi4 = reinterpret_cast<const float4*>(g_inter);
    for (int k = tid; k < TOP_K * INTER / 4; k += 256)
        gi_s[k] = gi4[k];
    __syncthreads();

    const int h = blockIdx.x * 4 + hloc;     // 0..2047

    const long long e0 = topk_idx[2 * p];
    const long long e1 = topk_idx[2 * p + 1];
    const float4* d0 = reinterpret_cast<const float4*>(
        down_all + (e0 * HIDDEN + h) * (long long)INTER);
    const float4* d1 = reinterpret_cast<const float4*>(
        down_all + (e1 * HIDDEN + h) * (long long)INTER);
    const float4* v0p = gi_s + 2 * p * 352;
    const float4* v1p = gi_s + (2 * p + 1) * 352;

    float acc0 = 0.f, acc1 = 0.f;
    // 352 float4 per expert row, 32 lanes -> 11 iterations x 2 experts
#pragma unroll
    for (int j = 0; j < 11; j++) {
        const int idx = j * 32 + lane;
        const float4 a0 = __ldg(d0 + idx);
        const float4 a1 = __ldg(d1 + idx);
        const float4 v0 = v0p[idx];
        const float4 v1 = v1p[idx];
        acc0 += a0.x * v0.x + a0.y * v0.y + a0.z * v0.z + a0.w * v0.w;
        acc1 += a1.x * v1.x + a1.y * v1.y + a1.z * v1.z + a1.w * v1.w;
    }

    float acc = acc0 + acc1;
#pragma unroll
    for (int off = 16; off > 0; off >>= 1)
        acc += __shfl_xor_sync(0xFFFFFFFFu, acc, off);

    if (lane == 0) partial[warp] = acc;
    __syncthreads();

    if (tid < 4)
        out[blockIdx.x * 4 + tid] = partial[2 * tid] + partial[2 * tid + 1];
}

extern "C" void kernel_launch(void* const* d_in, const int* in_sizes, int n_in,
                              void* d_out, int out_size)
{
    const float* x        = (const float*)d_in[0];   // (1, 2048, 1, 1)
    const int*   topk_idx = (const int*)  d_in[1];   // (4,)
    const float* topk_w   = (const float*)d_in[2];   // (4,)
    const float* gate_all = (const float*)d_in[3];   // (60, 1408, 2048)
    const float* up_all   = (const float*)d_in[4];   // (60, 1408, 2048)
    const float* down_all = (const float*)d_in[5];   // (60, 2048, 1408)
    float* out = (float*)d_out;                      // (1, 2048, 1, 1)

    dim3 grid1(INTER / 8, TOP_K);
    moe_gate_up_kernel<<<grid1, 256>>>(x, topk_idx, topk_w,
                                       gate_all, up_all, down_all);

    moe_down_kernel<<<HIDDEN / 4, 256>>>(topk_idx, down_all, out);
}